// round 2
// baseline (speedup 1.0000x reference)
#include <cuda_runtime.h>
#include <stdint.h>

// ---------------------------------------------------------------------------
// Problem constants
// ---------------------------------------------------------------------------
#define T_TOK 2048
#define HS    768
#define P_EXP 8
#define M_SUB 1024
#define D_EMB 512

// Output layout (float32, flattened concat of reference tuple)
#define OFF_WORD 0
#define OFF_PSR  (T_TOK)
#define OFF_ATK  (OFF_PSR + T_TOK * D_EMB)
#define OFF_ENT  (OFF_ATK + T_TOK * D_EMB)
#define OFF_CPY  (OFF_ENT + 1)
#define OFF_OBF  (OFF_CPY + T_TOK)
#define OFF_PRI  (OFF_OBF + T_TOK)

// ---------------------------------------------------------------------------
// Device scratch (no dynamic allocation allowed)
// ---------------------------------------------------------------------------
__device__ float g_spt[(size_t)T_TOK * M_SUB];   // logits, then overwritten by spt
__device__ int   g_cnt[P_EXP];
__device__ int   g_list[P_EXP][T_TOK];
__device__ float g_negent[T_TOK];

// ---------------------------------------------------------------------------
// K0: compact token indices per expert
// ---------------------------------------------------------------------------
__global__ void k0_compact(const int* __restrict__ inp_pos) {
    int tid = threadIdx.x;
    if (tid < P_EXP) g_cnt[tid] = 0;
    __syncthreads();
    for (int t = tid; t < T_TOK; t += blockDim.x) {
        int p = inp_pos[t];
        if (p < P_EXP) {
            int slot = atomicAdd(&g_cnt[p], 1);
            g_list[p][slot] = t;
        }
    }
}

// ---------------------------------------------------------------------------
// K1: logits[t, :] = ctx[t] @ dec_W[p] + dec_b[p]   (only target tokens)
// Tiled fp32 GEMM: BM=32 tokens, BN=128 cols, BK=16, 256 thr, 4x4 per thread
// ---------------------------------------------------------------------------
#define BM 32
#define BN 128
#define BK 16

__global__ __launch_bounds__(256) void k1_gemm(const float* __restrict__ ctx,
                                               const float* __restrict__ dec_W,
                                               const float* __restrict__ dec_b) {
    const int p  = blockIdx.z;
    const int mt = blockIdx.y;
    const int nt = blockIdx.x;
    const int cnt = g_cnt[p];
    if (mt * BM >= cnt) return;

    __shared__ __align__(16) float Xs[BK][BM];
    __shared__ __align__(16) float Ws[BK][BN];
    __shared__ int toks[BM];

    const int tid = threadIdx.x;
    if (tid < BM) {
        int r = mt * BM + tid;
        toks[tid] = (r < cnt) ? g_list[p][r] : -1;
    }
    __syncthreads();

    float acc[4][4] = {};
    const int tx = tid & 31;   // column group
    const int ty = tid >> 5;   // row group (0..7)

    const float* Wp = dec_W + (size_t)p * HS * M_SUB + nt * BN;

    for (int k0 = 0; k0 < HS; k0 += BK) {
        // X tile: consecutive tid -> consecutive k within a token row (coalesced 64B)
        #pragma unroll
        for (int i = tid; i < BK * BM; i += 256) {
            int r = i >> 4, kk = i & 15;
            int tok = toks[r];
            Xs[kk][r] = (tok >= 0) ? ctx[(size_t)tok * HS + k0 + kk] : 0.0f;
        }
        // W tile: fully coalesced over columns
        #pragma unroll
        for (int i = tid; i < BK * BN; i += 256) {
            int kk = i >> 7, c = i & 127;
            Ws[kk][c] = Wp[(size_t)(k0 + kk) * M_SUB + c];
        }
        __syncthreads();

        #pragma unroll
        for (int kk = 0; kk < BK; kk++) {
            float4 xv = *reinterpret_cast<const float4*>(&Xs[kk][ty * 4]);
            float4 wv = *reinterpret_cast<const float4*>(&Ws[kk][tx * 4]);
            float xa[4] = {xv.x, xv.y, xv.z, xv.w};
            float wa[4] = {wv.x, wv.y, wv.z, wv.w};
            #pragma unroll
            for (int i = 0; i < 4; i++)
                #pragma unroll
                for (int j = 0; j < 4; j++)
                    acc[i][j] += xa[i] * wa[j];
        }
        __syncthreads();
    }

    const int cbase = nt * BN + tx * 4;
    #pragma unroll
    for (int i = 0; i < 4; i++) {
        int tok = toks[ty * 4 + i];
        if (tok < 0) continue;
        float* o = g_spt + (size_t)tok * M_SUB + cbase;
        #pragma unroll
        for (int j = 0; j < 4; j++)
            o[j] = acc[i][j] + dec_b[p * M_SUB + cbase + j];
    }
}

// ---------------------------------------------------------------------------
// Block reductions (256 threads, deterministic)
// ---------------------------------------------------------------------------
__device__ __forceinline__ float blockMax256(float v, volatile float* red, int tid) {
    int lane = tid & 31;
    #pragma unroll
    for (int o = 16; o > 0; o >>= 1)
        v = fmaxf(v, __shfl_xor_sync(0xffffffffu, v, o));
    __syncthreads();
    if (lane == 0) red[tid >> 5] = v;
    __syncthreads();
    float r = red[0];
    #pragma unroll
    for (int i = 1; i < 8; i++) r = fmaxf(r, red[i]);
    return r;
}

__device__ __forceinline__ float blockSum256(float v, volatile float* red, int tid) {
    int lane = tid & 31;
    #pragma unroll
    for (int o = 16; o > 0; o >>= 1)
        v += __shfl_xor_sync(0xffffffffu, v, o);
    __syncthreads();
    if (lane == 0) red[tid >> 5] = v;
    __syncthreads();
    float r = red[0];
    #pragma unroll
    for (int i = 1; i < 8; i++) r += red[i];
    return r;
}

__device__ __forceinline__ void blockArgMax256(float& v, int& idx,
                                               volatile float* red, volatile int* redi,
                                               int tid) {
    int lane = tid & 31;
    #pragma unroll
    for (int o = 16; o > 0; o >>= 1) {
        float ov = __shfl_xor_sync(0xffffffffu, v, o);
        int   oi = __shfl_xor_sync(0xffffffffu, idx, o);
        if (ov > v || (ov == v && oi < idx)) { v = ov; idx = oi; }
    }
    __syncthreads();
    if (lane == 0) { red[tid >> 5] = v; redi[tid >> 5] = idx; }
    __syncthreads();
    float bv = red[0]; int bi = redi[0];
    #pragma unroll
    for (int i = 1; i < 8; i++) {
        float ov = red[i]; int oi = redi[i];
        if (ov > bv || (ov == bv && oi < bi)) { bv = ov; bi = oi; }
    }
    v = bv; idx = bi;
}

// ---------------------------------------------------------------------------
// K2: per-token row ops: logsumexp, entropy, gumbel-softmax, argmax,
//     writes spt in place; copy-through path for non-target tokens.
// NOTE: inp_mask arrives as int32 (JAX bool -> i32 in the harness buffer).
// ---------------------------------------------------------------------------
__global__ __launch_bounds__(256) void k2_row(const int* __restrict__ inp_word,
                                              const int* __restrict__ inp_pos,
                                              const int* __restrict__ inp_mask,
                                              const float* __restrict__ u_gum,
                                              const int* __restrict__ words,
                                              const float* __restrict__ psr_w,
                                              const float* __restrict__ atk_w,
                                              float* __restrict__ out) {
    const int t   = blockIdx.x;
    const int tid = threadIdx.x;
    const int w0  = inp_word[t];
    const int p   = inp_pos[t];
    const bool mk = inp_mask[t] != 0;

    if (p >= P_EXP) {
        // copy-through token
        if (tid == 0) {
            out[OFF_WORD + t] = (float)w0;
            out[OFF_CPY + t]  = mk ? 1.0f : 0.0f;
            out[OFF_OBF + t]  = 0.0f;
            out[OFF_PRI + t]  = 0.0f;
        }
        const float* ps = psr_w + (size_t)w0 * D_EMB;
        const float* as = atk_w + (size_t)w0 * D_EMB;
        float* po = out + OFF_PSR + (size_t)t * D_EMB;
        float* ao = out + OFF_ATK + (size_t)t * D_EMB;
        for (int d = tid; d < D_EMB; d += 256) { po[d] = ps[d]; ao[d] = as[d]; }
        return;
    }

    __shared__ float red[8];
    __shared__ int   redi[8];

    float* row = g_spt + (size_t)t * M_SUB;

    float l[4], z[4];
    #pragma unroll
    for (int k = 0; k < 4; k++) {
        int i = tid + k * 256;
        l[k] = row[i];
        float uu = u_gum[(size_t)t * M_SUB + i];
        uu = fminf(fmaxf(uu, 1e-6f), 1.0f - 1e-6f);
        z[k] = l[k] - logf(-logf(uu));   // logits + gumbel
    }

    // log-softmax
    float m1 = fmaxf(fmaxf(l[0], l[1]), fmaxf(l[2], l[3]));
    m1 = blockMax256(m1, red, tid);
    float s1 = 0.0f;
    #pragma unroll
    for (int k = 0; k < 4; k++) s1 += expf(l[k] - m1);
    s1 = blockSum256(s1, red, tid);
    const float lse = m1 + logf(s1);

    // entropy term: sum pspt * exp(pspt)
    float se = 0.0f;
    #pragma unroll
    for (int k = 0; k < 4; k++) {
        float ps = l[k] - lse;
        se += ps * expf(ps);
    }
    se = blockSum256(se, red, tid);
    if (tid == 0) g_negent[t] = -se;

    // gumbel softmax: argmax + normalize
    float mv = z[0]; int midx = tid;
    #pragma unroll
    for (int k = 1; k < 4; k++) {
        if (z[k] > mv) { mv = z[k]; midx = tid + k * 256; }
    }
    blockArgMax256(mv, midx, red, redi, tid);

    float s2 = 0.0f;
    #pragma unroll
    for (int k = 0; k < 4; k++) s2 += expf(z[k] - mv);
    s2 = blockSum256(s2, red, tid);
    const float inv = 1.0f / s2;
    #pragma unroll
    for (int k = 0; k < 4; k++)
        row[tid + k * 256] = expf(z[k] - mv) * inv;

    if (tid == 0) {
        int aw = words[p * M_SUB + midx];
        out[OFF_WORD + t] = (float)aw;
        out[OFF_CPY + t]  = (aw == w0 && mk) ? 1.0f : 0.0f;
        out[OFF_OBF + t]  = 1.0f;
        out[OFF_PRI + t]  = (p < 4) ? 1.0f : 0.0f;
    }
}

// ---------------------------------------------------------------------------
// K3: psr/atk embedding mix: out[t, d] = sum_m spt[t,m] * table[words[p,m], d]
// Combined N = 1024 (cols 0..511 -> psr, 512..1023 -> atk). Gathered B tile.
// ---------------------------------------------------------------------------
__global__ __launch_bounds__(256) void k3_gemm(const float* __restrict__ psr_w,
                                               const float* __restrict__ atk_w,
                                               const int* __restrict__ words,
                                               float* __restrict__ out) {
    const int p  = blockIdx.z;
    const int mt = blockIdx.y;
    const int nt = blockIdx.x;   // 0..7 over combined 1024 columns
    const int cnt = g_cnt[p];
    if (mt * BM >= cnt) return;

    __shared__ __align__(16) float As[BK][BM];
    __shared__ __align__(16) float Bs[BK][BN];
    __shared__ int toks[BM];

    const int tid = threadIdx.x;
    if (tid < BM) {
        int r = mt * BM + tid;
        toks[tid] = (r < cnt) ? g_list[p][r] : -1;
    }
    __syncthreads();

    float acc[4][4] = {};
    const int tx = tid & 31;
    const int ty = tid >> 5;

    const int cbase = nt * BN;
    const bool is_psr = (cbase < D_EMB);
    const float* tab  = is_psr ? psr_w : atk_w;
    const int dbase   = is_psr ? cbase : (cbase - D_EMB);
    const int* wp     = words + p * M_SUB;

    for (int k0 = 0; k0 < M_SUB; k0 += BK) {
        #pragma unroll
        for (int i = tid; i < BK * BM; i += 256) {
            int r = i >> 4, kk = i & 15;
            int tok = toks[r];
            As[kk][r] = (tok >= 0) ? g_spt[(size_t)tok * M_SUB + k0 + kk] : 0.0f;
        }
        #pragma unroll
        for (int i = tid; i < BK * BN; i += 256) {
            int kk = i >> 7, c = i & 127;
            int wr = __ldg(&wp[k0 + kk]);
            Bs[kk][c] = tab[(size_t)wr * D_EMB + dbase + c];
        }
        __syncthreads();

        #pragma unroll
        for (int kk = 0; kk < BK; kk++) {
            float4 xv = *reinterpret_cast<const float4*>(&As[kk][ty * 4]);
            float4 wv = *reinterpret_cast<const float4*>(&Bs[kk][tx * 4]);
            float xa[4] = {xv.x, xv.y, xv.z, xv.w};
            float wa[4] = {wv.x, wv.y, wv.z, wv.w};
            #pragma unroll
            for (int i = 0; i < 4; i++)
                #pragma unroll
                for (int j = 0; j < 4; j++)
                    acc[i][j] += xa[i] * wa[j];
        }
        __syncthreads();
    }

    const size_t obase = (is_psr ? (size_t)OFF_PSR : (size_t)OFF_ATK);
    const int dcol = dbase + tx * 4;
    #pragma unroll
    for (int i = 0; i < 4; i++) {
        int tok = toks[ty * 4 + i];
        if (tok < 0) continue;
        float* o = out + obase + (size_t)tok * D_EMB + dcol;
        #pragma unroll
        for (int j = 0; j < 4; j++) o[j] = acc[i][j];
    }
}

// ---------------------------------------------------------------------------
// K4: deterministic entropy finalize
// ---------------------------------------------------------------------------
__global__ void k4_ent(const int* __restrict__ inp_pos, float* __restrict__ out) {
    __shared__ float sh[256];
    __shared__ int   shc[256];
    __shared__ float ent_s;
    const int tid = threadIdx.x;
    if (tid == 0) ent_s = 0.0f;

    for (int p = 0; p < P_EXP; p++) {
        float s = 0.0f; int c = 0;
        for (int t = tid; t < T_TOK; t += 256) {
            if (inp_pos[t] == p) { s += g_negent[t]; c++; }
        }
        sh[tid] = s; shc[tid] = c;
        __syncthreads();
        for (int o = 128; o > 0; o >>= 1) {
            if (tid < o) { sh[tid] += sh[tid + o]; shc[tid] += shc[tid + o]; }
            __syncthreads();
        }
        if (tid == 0 && shc[0] > 0)
            ent_s += sh[0] / ((float)shc[0] * (float)M_SUB);
        __syncthreads();
    }
    if (tid == 0) out[OFF_ENT] = -ent_s;
}

// ---------------------------------------------------------------------------
// Entry point
// ---------------------------------------------------------------------------
extern "C" void kernel_launch(void* const* d_in, const int* in_sizes, int n_in,
                              void* d_out, int out_size) {
    const int*      inp_word = (const int*)d_in[0];
    const int*      inp_pos  = (const int*)d_in[1];
    const int*      inp_mask = (const int*)d_in[2];   // JAX bool -> int32
    const float*    ctx      = (const float*)d_in[3];
    const float*    dec_W    = (const float*)d_in[4];
    const float*    dec_b    = (const float*)d_in[5];
    const float*    psr_w    = (const float*)d_in[6];
    const float*    atk_w    = (const float*)d_in[7];
    const int*      words    = (const int*)d_in[8];
    const float*    u_gum    = (const float*)d_in[9];
    float*          out      = (float*)d_out;

    (void)in_sizes; (void)n_in; (void)out_size;

    k0_compact<<<1, 256>>>(inp_pos);
    k1_gemm<<<dim3(M_SUB / BN, T_TOK / BM, P_EXP), 256>>>(ctx, dec_W, dec_b);
    k2_row<<<T_TOK, 256>>>(inp_word, inp_pos, inp_mask, u_gum, words,
                           psr_w, atk_w, out);
    k3_gemm<<<dim3((2 * D_EMB) / BN, T_TOK / BM, P_EXP), 256>>>(psr_w, atk_w,
                                                                words, out);
    k4_ent<<<1, 256>>>(inp_pos, out);
}

// round 3
// speedup vs baseline: 1.1670x; 1.1670x over previous
#include <cuda_runtime.h>
#include <stdint.h>

// ---------------------------------------------------------------------------
// Problem constants
// ---------------------------------------------------------------------------
#define T_TOK 2048
#define HS    768
#define P_EXP 8
#define M_SUB 1024
#define D_EMB 512

// Output layout (float32, flattened concat of reference tuple)
#define OFF_WORD 0
#define OFF_PSR  (T_TOK)
#define OFF_ATK  (OFF_PSR + T_TOK * D_EMB)
#define OFF_ENT  (OFF_ATK + T_TOK * D_EMB)
#define OFF_CPY  (OFF_ENT + 1)
#define OFF_OBF  (OFF_CPY + T_TOK)
#define OFF_PRI  (OFF_OBF + T_TOK)

// GEMM tiling
#define BM 64
#define BN 64
#define BK 16

// ---------------------------------------------------------------------------
// Device scratch
// ---------------------------------------------------------------------------
__device__ float g_spt[(size_t)T_TOK * M_SUB];   // logits, then spt (in place)
__device__ int   g_cnt[P_EXP];
__device__ int   g_list[P_EXP][T_TOK];
__device__ float g_negent[T_TOK];

// ---------------------------------------------------------------------------
// K0: compact token indices per expert
// ---------------------------------------------------------------------------
__global__ void k0_compact(const int* __restrict__ inp_pos) {
    int tid = threadIdx.x;
    if (tid < P_EXP) g_cnt[tid] = 0;
    __syncthreads();
    for (int t = tid; t < T_TOK; t += blockDim.x) {
        int p = inp_pos[t];
        if (p < P_EXP) {
            int slot = atomicAdd(&g_cnt[p], 1);
            g_list[p][slot] = t;
        }
    }
}

// ---------------------------------------------------------------------------
// K1: logits = ctx[toks] @ dec_W[p] + dec_b[p]
// BM=64 tokens x BN=64 cols, BK=16, 256 threads, 4x4 microtile,
// 2D lane layout (A-frag broadcast), double-buffered smem, 1 sync/iter.
// ---------------------------------------------------------------------------
__global__ __launch_bounds__(256) void k1_gemm(const float* __restrict__ ctx,
                                               const float* __restrict__ dec_W,
                                               const float* __restrict__ dec_b) {
    const int p  = blockIdx.z;
    const int mt = blockIdx.y;
    const int nt = blockIdx.x;
    const int cnt = g_cnt[p];
    if (mt * BM >= cnt) return;

    __shared__ __align__(16) float Xs[2][BK][BM];
    __shared__ __align__(16) float Ws[2][BK][BN];
    __shared__ int toks[BM];

    const int tid = threadIdx.x;
    if (tid < BM) {
        int r = mt * BM + tid;
        toks[tid] = (r < cnt) ? g_list[p][r] : -1;
    }
    __syncthreads();

    // thread-tile coordinates: warp w, lane layout 4 (rows) x 8 (cols)
    const int w    = tid >> 5;
    const int wm   = w & 3;            // 4 warps along M
    const int wn   = w >> 2;           // 2 warps along N
    const int lr   = (tid >> 3) & 3;   // lane row group
    const int lc   = tid & 7;          // lane col group
    const int row0 = wm * 16 + lr * 4; // 0..60
    const int col0 = wn * 32 + lc * 4; // 0..60

    // gmem load roles
    const int am  = tid >> 2;          // 0..63 (token row within tile)
    const int akq = tid & 3;           // which float4 of the 16 k's
    const int bkk = tid >> 4;          // 0..15 (k row of W tile)
    const int bc4 = tid & 15;          // 0..15 (float4 column)

    const int atok = toks[am];
    const float* Wp = dec_W + (size_t)p * HS * M_SUB + nt * BN;

    float4 ra, rb;
    // prefetch tile 0
    {
        ra = (atok >= 0)
           ? *reinterpret_cast<const float4*>(&ctx[(size_t)atok * HS + akq * 4])
           : make_float4(0.f, 0.f, 0.f, 0.f);
        rb = *reinterpret_cast<const float4*>(&Wp[(size_t)bkk * M_SUB + bc4 * 4]);
    }
    {
        Xs[0][akq * 4 + 0][am] = ra.x;
        Xs[0][akq * 4 + 1][am] = ra.y;
        Xs[0][akq * 4 + 2][am] = ra.z;
        Xs[0][akq * 4 + 3][am] = ra.w;
        *reinterpret_cast<float4*>(&Ws[0][bkk][bc4 * 4]) = rb;
    }
    __syncthreads();

    float acc[4][4] = {};
    const int NIT = HS / BK;  // 48

    for (int it = 0; it < NIT; it++) {
        const int cur = it & 1, nxt = cur ^ 1;
        const int k0n = (it + 1) * BK;
        if (it + 1 < NIT) {
            ra = (atok >= 0)
               ? *reinterpret_cast<const float4*>(&ctx[(size_t)atok * HS + k0n + akq * 4])
               : make_float4(0.f, 0.f, 0.f, 0.f);
            rb = *reinterpret_cast<const float4*>(&Wp[(size_t)(k0n + bkk) * M_SUB + bc4 * 4]);
        }
        #pragma unroll
        for (int kk = 0; kk < BK; kk++) {
            float4 av = *reinterpret_cast<const float4*>(&Xs[cur][kk][row0]);
            float4 bv = *reinterpret_cast<const float4*>(&Ws[cur][kk][col0]);
            float a4[4] = {av.x, av.y, av.z, av.w};
            float b4[4] = {bv.x, bv.y, bv.z, bv.w};
            #pragma unroll
            for (int i = 0; i < 4; i++)
                #pragma unroll
                for (int j = 0; j < 4; j++)
                    acc[i][j] += a4[i] * b4[j];
        }
        if (it + 1 < NIT) {
            Xs[nxt][akq * 4 + 0][am] = ra.x;
            Xs[nxt][akq * 4 + 1][am] = ra.y;
            Xs[nxt][akq * 4 + 2][am] = ra.z;
            Xs[nxt][akq * 4 + 3][am] = ra.w;
            *reinterpret_cast<float4*>(&Ws[nxt][bkk][bc4 * 4]) = rb;
        }
        __syncthreads();
    }

    const int cbase = nt * BN + col0;
    const float* bp = dec_b + p * M_SUB + cbase;
    #pragma unroll
    for (int i = 0; i < 4; i++) {
        int tok = toks[row0 + i];
        if (tok < 0) continue;
        float* o = g_spt + (size_t)tok * M_SUB + cbase;
        #pragma unroll
        for (int j = 0; j < 4; j++)
            o[j] = acc[i][j] + bp[j];
    }
}

// ---------------------------------------------------------------------------
// Block reductions (256 threads)
// ---------------------------------------------------------------------------
__device__ __forceinline__ float blockMax256(float v, volatile float* red, int tid) {
    int lane = tid & 31;
    #pragma unroll
    for (int o = 16; o > 0; o >>= 1)
        v = fmaxf(v, __shfl_xor_sync(0xffffffffu, v, o));
    __syncthreads();
    if (lane == 0) red[tid >> 5] = v;
    __syncthreads();
    float r = red[0];
    #pragma unroll
    for (int i = 1; i < 8; i++) r = fmaxf(r, red[i]);
    return r;
}

__device__ __forceinline__ float blockSum256(float v, volatile float* red, int tid) {
    int lane = tid & 31;
    #pragma unroll
    for (int o = 16; o > 0; o >>= 1)
        v += __shfl_xor_sync(0xffffffffu, v, o);
    __syncthreads();
    if (lane == 0) red[tid >> 5] = v;
    __syncthreads();
    float r = red[0];
    #pragma unroll
    for (int i = 1; i < 8; i++) r += red[i];
    return r;
}

__device__ __forceinline__ void blockArgMax256(float& v, int& idx,
                                               volatile float* red, volatile int* redi,
                                               int tid) {
    int lane = tid & 31;
    #pragma unroll
    for (int o = 16; o > 0; o >>= 1) {
        float ov = __shfl_xor_sync(0xffffffffu, v, o);
        int   oi = __shfl_xor_sync(0xffffffffu, idx, o);
        if (ov > v || (ov == v && oi < idx)) { v = ov; idx = oi; }
    }
    __syncthreads();
    if (lane == 0) { red[tid >> 5] = v; redi[tid >> 5] = idx; }
    __syncthreads();
    float bv = red[0]; int bi = redi[0];
    #pragma unroll
    for (int i = 1; i < 8; i++) {
        float ov = red[i]; int oi = redi[i];
        if (ov > bv || (ov == bv && oi < bi)) { bv = ov; bi = oi; }
    }
    v = bv; idx = bi;
}

// ---------------------------------------------------------------------------
// K2: per-token row ops (float4-vectorized)
// ---------------------------------------------------------------------------
__global__ __launch_bounds__(256) void k2_row(const int* __restrict__ inp_word,
                                              const int* __restrict__ inp_pos,
                                              const int* __restrict__ inp_mask,
                                              const float* __restrict__ u_gum,
                                              const int* __restrict__ words,
                                              const float* __restrict__ psr_w,
                                              const float* __restrict__ atk_w,
                                              float* __restrict__ out) {
    const int t   = blockIdx.x;
    const int tid = threadIdx.x;
    const int w0  = inp_word[t];
    const int p   = inp_pos[t];
    const bool mk = inp_mask[t] != 0;

    if (p >= P_EXP) {
        if (tid == 0) {
            out[OFF_WORD + t] = (float)w0;
            out[OFF_CPY + t]  = mk ? 1.0f : 0.0f;
            out[OFF_OBF + t]  = 0.0f;
            out[OFF_PRI + t]  = 0.0f;
        }
        const float4* ps = (const float4*)(psr_w + (size_t)w0 * D_EMB);
        const float4* as = (const float4*)(atk_w + (size_t)w0 * D_EMB);
        float4* po = (float4*)(out + OFF_PSR + (size_t)t * D_EMB);
        float4* ao = (float4*)(out + OFF_ATK + (size_t)t * D_EMB);
        for (int d = tid; d < D_EMB / 4; d += 256) { po[d] = ps[d]; ao[d] = as[d]; }
        return;
    }

    __shared__ float red[8];
    __shared__ int   redi[8];

    float4* rowv = (float4*)(g_spt + (size_t)t * M_SUB);
    const float4* uv = (const float4*)(u_gum + (size_t)t * M_SUB);

    float4 lv = rowv[tid];
    float4 uu4 = uv[tid];
    float l[4] = {lv.x, lv.y, lv.z, lv.w};
    float u4[4] = {uu4.x, uu4.y, uu4.z, uu4.w};
    float z[4];
    #pragma unroll
    for (int k = 0; k < 4; k++) {
        float uu = fminf(fmaxf(u4[k], 1e-6f), 1.0f - 1e-6f);
        z[k] = l[k] - logf(-logf(uu));
    }

    // log-softmax over logits
    float m1 = fmaxf(fmaxf(l[0], l[1]), fmaxf(l[2], l[3]));
    m1 = blockMax256(m1, red, tid);
    float s1 = 0.0f;
    #pragma unroll
    for (int k = 0; k < 4; k++) s1 += expf(l[k] - m1);
    s1 = blockSum256(s1, red, tid);
    const float lse = m1 + logf(s1);

    // entropy term
    float se = 0.0f;
    #pragma unroll
    for (int k = 0; k < 4; k++) {
        float ps = l[k] - lse;
        se += ps * expf(ps);
    }
    se = blockSum256(se, red, tid);
    if (tid == 0) g_negent[t] = -se;

    // gumbel softmax: argmax + normalize
    float mv = z[0]; int midx = tid * 4;
    #pragma unroll
    for (int k = 1; k < 4; k++) {
        if (z[k] > mv) { mv = z[k]; midx = tid * 4 + k; }
    }
    blockArgMax256(mv, midx, red, redi, tid);

    float s2 = 0.0f;
    #pragma unroll
    for (int k = 0; k < 4; k++) s2 += expf(z[k] - mv);
    s2 = blockSum256(s2, red, tid);
    const float inv = 1.0f / s2;
    float4 sv;
    sv.x = expf(z[0] - mv) * inv;
    sv.y = expf(z[1] - mv) * inv;
    sv.z = expf(z[2] - mv) * inv;
    sv.w = expf(z[3] - mv) * inv;
    rowv[tid] = sv;

    if (tid == 0) {
        int aw = words[p * M_SUB + midx];
        out[OFF_WORD + t] = (float)aw;
        out[OFF_CPY + t]  = (aw == w0 && mk) ? 1.0f : 0.0f;
        out[OFF_OBF + t]  = 1.0f;
        out[OFF_PRI + t]  = (p < 4) ? 1.0f : 0.0f;
    }
}

// ---------------------------------------------------------------------------
// K3: out[t, :] = spt[t] @ gather(table, words[p])  (combined psr|atk columns)
// Same GEMM structure as K1; B rows gathered via words.
// ---------------------------------------------------------------------------
__global__ __launch_bounds__(256) void k3_gemm(const float* __restrict__ psr_w,
                                               const float* __restrict__ atk_w,
                                               const int* __restrict__ words,
                                               float* __restrict__ out) {
    const int p  = blockIdx.z;
    const int mt = blockIdx.y;
    const int nt = blockIdx.x;   // 0..15 over combined 1024 columns
    const int cnt = g_cnt[p];
    if (mt * BM >= cnt) return;

    __shared__ __align__(16) float As[2][BK][BM];
    __shared__ __align__(16) float Bs[2][BK][BN];
    __shared__ int toks[BM];

    const int tid = threadIdx.x;
    if (tid < BM) {
        int r = mt * BM + tid;
        toks[tid] = (r < cnt) ? g_list[p][r] : -1;
    }
    __syncthreads();

    const int w    = tid >> 5;
    const int wm   = w & 3;
    const int wn   = w >> 2;
    const int lr   = (tid >> 3) & 3;
    const int lc   = tid & 7;
    const int row0 = wm * 16 + lr * 4;
    const int col0 = wn * 32 + lc * 4;

    const int am  = tid >> 2;
    const int akq = tid & 3;
    const int bkk = tid >> 4;
    const int bc4 = tid & 15;

    const int atok = toks[am];

    const int cbase0  = nt * BN;
    const bool is_psr = (cbase0 < D_EMB);
    const float* tab  = is_psr ? psr_w : atk_w;
    const int dbase   = is_psr ? cbase0 : (cbase0 - D_EMB);
    const int* wp     = words + p * M_SUB;

    float4 ra, rb;
    {
        ra = (atok >= 0)
           ? *reinterpret_cast<const float4*>(&g_spt[(size_t)atok * M_SUB + akq * 4])
           : make_float4(0.f, 0.f, 0.f, 0.f);
        int wr = __ldg(&wp[bkk]);
        rb = *reinterpret_cast<const float4*>(&tab[(size_t)wr * D_EMB + dbase + bc4 * 4]);
    }
    {
        As[0][akq * 4 + 0][am] = ra.x;
        As[0][akq * 4 + 1][am] = ra.y;
        As[0][akq * 4 + 2][am] = ra.z;
        As[0][akq * 4 + 3][am] = ra.w;
        *reinterpret_cast<float4*>(&Bs[0][bkk][bc4 * 4]) = rb;
    }
    __syncthreads();

    float acc[4][4] = {};
    const int NIT = M_SUB / BK;  // 64

    for (int it = 0; it < NIT; it++) {
        const int cur = it & 1, nxt = cur ^ 1;
        const int k0n = (it + 1) * BK;
        if (it + 1 < NIT) {
            ra = (atok >= 0)
               ? *reinterpret_cast<const float4*>(&g_spt[(size_t)atok * M_SUB + k0n + akq * 4])
               : make_float4(0.f, 0.f, 0.f, 0.f);
            int wr = __ldg(&wp[k0n + bkk]);
            rb = *reinterpret_cast<const float4*>(&tab[(size_t)wr * D_EMB + dbase + bc4 * 4]);
        }
        #pragma unroll
        for (int kk = 0; kk < BK; kk++) {
            float4 av = *reinterpret_cast<const float4*>(&As[cur][kk][row0]);
            float4 bv = *reinterpret_cast<const float4*>(&Bs[cur][kk][col0]);
            float a4[4] = {av.x, av.y, av.z, av.w};
            float b4[4] = {bv.x, bv.y, bv.z, bv.w};
            #pragma unroll
            for (int i = 0; i < 4; i++)
                #pragma unroll
                for (int j = 0; j < 4; j++)
                    acc[i][j] += a4[i] * b4[j];
        }
        if (it + 1 < NIT) {
            As[nxt][akq * 4 + 0][am] = ra.x;
            As[nxt][akq * 4 + 1][am] = ra.y;
            As[nxt][akq * 4 + 2][am] = ra.z;
            As[nxt][akq * 4 + 3][am] = ra.w;
            *reinterpret_cast<float4*>(&Bs[nxt][bkk][bc4 * 4]) = rb;
        }
        __syncthreads();
    }

    const size_t obase = (is_psr ? (size_t)OFF_PSR : (size_t)OFF_ATK);
    const int dcol = dbase + col0;
    #pragma unroll
    for (int i = 0; i < 4; i++) {
        int tok = toks[row0 + i];
        if (tok < 0) continue;
        float* o = out + obase + (size_t)tok * D_EMB + dcol;
        #pragma unroll
        for (int j = 0; j < 4; j++) o[j] = acc[i][j];
    }
}

// ---------------------------------------------------------------------------
// K4: deterministic entropy finalize
// ---------------------------------------------------------------------------
__global__ void k4_ent(const int* __restrict__ inp_pos, float* __restrict__ out) {
    __shared__ float sh[256];
    __shared__ int   shc[256];
    __shared__ float ent_s;
    const int tid = threadIdx.x;
    if (tid == 0) ent_s = 0.0f;

    for (int p = 0; p < P_EXP; p++) {
        float s = 0.0f; int c = 0;
        for (int t = tid; t < T_TOK; t += 256) {
            if (inp_pos[t] == p) { s += g_negent[t]; c++; }
        }
        sh[tid] = s; shc[tid] = c;
        __syncthreads();
        for (int o = 128; o > 0; o >>= 1) {
            if (tid < o) { sh[tid] += sh[tid + o]; shc[tid] += shc[tid + o]; }
            __syncthreads();
        }
        if (tid == 0 && shc[0] > 0)
            ent_s += sh[0] / ((float)shc[0] * (float)M_SUB);
        __syncthreads();
    }
    if (tid == 0) out[OFF_ENT] = -ent_s;
}

// ---------------------------------------------------------------------------
// Entry point
// ---------------------------------------------------------------------------
extern "C" void kernel_launch(void* const* d_in, const int* in_sizes, int n_in,
                              void* d_out, int out_size) {
    const int*      inp_word = (const int*)d_in[0];
    const int*      inp_pos  = (const int*)d_in[1];
    const int*      inp_mask = (const int*)d_in[2];   // JAX bool -> int32
    const float*    ctx      = (const float*)d_in[3];
    const float*    dec_W    = (const float*)d_in[4];
    const float*    dec_b    = (const float*)d_in[5];
    const float*    psr_w    = (const float*)d_in[6];
    const float*    atk_w    = (const float*)d_in[7];
    const int*      words    = (const int*)d_in[8];
    const float*    u_gum    = (const float*)d_in[9];
    float*          out      = (float*)d_out;

    (void)in_sizes; (void)n_in; (void)out_size;

    k0_compact<<<1, 256>>>(inp_pos);
    k1_gemm<<<dim3(M_SUB / BN, T_TOK / BM, P_EXP), 256>>>(ctx, dec_W, dec_b);
    k2_row<<<T_TOK, 256>>>(inp_word, inp_pos, inp_mask, u_gum, words,
                           psr_w, atk_w, out);
    k3_gemm<<<dim3((2 * D_EMB) / BN, T_TOK / BM, P_EXP), 256>>>(psr_w, atk_w,
                                                                words, out);
    k4_ent<<<1, 256>>>(inp_pos, out);
}

// round 4
// speedup vs baseline: 1.1691x; 1.0017x over previous
#include <cuda_runtime.h>
#include <stdint.h>

// ---------------------------------------------------------------------------
// Problem constants
// ---------------------------------------------------------------------------
#define T_TOK 2048
#define HS    768
#define P_EXP 8
#define M_SUB 1024
#define D_EMB 512

// Output layout (float32, flattened concat of reference tuple)
#define OFF_WORD 0
#define OFF_PSR  (T_TOK)
#define OFF_ATK  (OFF_PSR + T_TOK * D_EMB)
#define OFF_ENT  (OFF_ATK + T_TOK * D_EMB)
#define OFF_CPY  (OFF_ENT + 1)
#define OFF_OBF  (OFF_CPY + T_TOK)
#define OFF_PRI  (OFF_OBF + T_TOK)

// GEMM tiling
#define BM 64
#define BN 64
#define BK 16

// packed fp32x2 helpers (Blackwell-native; ptxas never emits these from C++)
__device__ __forceinline__ unsigned long long pack2(float lo, float hi) {
    unsigned long long r;
    asm("mov.b64 %0, {%1, %2};" : "=l"(r) : "f"(lo), "f"(hi));
    return r;
}
__device__ __forceinline__ void unpack2(unsigned long long v, float& lo, float& hi) {
    asm("mov.b64 {%0, %1}, %2;" : "=f"(lo), "=f"(hi) : "l"(v));
}
__device__ __forceinline__ unsigned long long fma2(unsigned long long a,
                                                   unsigned long long b,
                                                   unsigned long long c) {
    unsigned long long d;
    asm("fma.rn.f32x2 %0, %1, %2, %3;" : "=l"(d) : "l"(a), "l"(b), "l"(c));
    return d;
}

// ---------------------------------------------------------------------------
// Device scratch
// ---------------------------------------------------------------------------
__device__ float g_spt[(size_t)T_TOK * M_SUB];   // logits, then spt (in place)
__device__ int   g_cnt[P_EXP];
__device__ int   g_list[P_EXP][T_TOK];
__device__ float g_negent[T_TOK];

// ---------------------------------------------------------------------------
// K0: compact token indices per expert
// ---------------------------------------------------------------------------
__global__ void k0_compact(const int* __restrict__ inp_pos) {
    int tid = threadIdx.x;
    if (tid < P_EXP) g_cnt[tid] = 0;
    __syncthreads();
    for (int t = tid; t < T_TOK; t += blockDim.x) {
        int p = inp_pos[t];
        if (p < P_EXP) {
            int slot = atomicAdd(&g_cnt[p], 1);
            g_list[p][slot] = t;
        }
    }
}

// ---------------------------------------------------------------------------
// Shared GEMM microkernel body (f32x2): acc[i][jp] over 4 rows x 2 col-pairs
// ---------------------------------------------------------------------------
#define MICRO_FMA2(Xsb, Wsb)                                                   \
    _Pragma("unroll")                                                          \
    for (int kk = 0; kk < BK; kk++) {                                          \
        float4 av = *reinterpret_cast<const float4*>(&Xsb[kk][row0]);          \
        float4 bv = *reinterpret_cast<const float4*>(&Wsb[kk][col0]);          \
        unsigned long long bp0 = pack2(bv.x, bv.y);                            \
        unsigned long long bp1 = pack2(bv.z, bv.w);                            \
        unsigned long long aa0 = pack2(av.x, av.x);                            \
        unsigned long long aa1 = pack2(av.y, av.y);                            \
        unsigned long long aa2 = pack2(av.z, av.z);                            \
        unsigned long long aa3 = pack2(av.w, av.w);                            \
        acc[0][0] = fma2(aa0, bp0, acc[0][0]);                                 \
        acc[0][1] = fma2(aa0, bp1, acc[0][1]);                                 \
        acc[1][0] = fma2(aa1, bp0, acc[1][0]);                                 \
        acc[1][1] = fma2(aa1, bp1, acc[1][1]);                                 \
        acc[2][0] = fma2(aa2, bp0, acc[2][0]);                                 \
        acc[2][1] = fma2(aa2, bp1, acc[2][1]);                                 \
        acc[3][0] = fma2(aa3, bp0, acc[3][0]);                                 \
        acc[3][1] = fma2(aa3, bp1, acc[3][1]);                                 \
    }

// ---------------------------------------------------------------------------
// K1: logits = ctx[toks] @ dec_W[p] + dec_b[p]
// ---------------------------------------------------------------------------
__global__ __launch_bounds__(256) void k1_gemm(const float* __restrict__ ctx,
                                               const float* __restrict__ dec_W,
                                               const float* __restrict__ dec_b) {
    const int p  = blockIdx.z;
    const int mt = blockIdx.y;
    const int nt = blockIdx.x;
    const int cnt = g_cnt[p];
    if (mt * BM >= cnt) return;

    __shared__ __align__(16) float Xs[2][BK][BM];
    __shared__ __align__(16) float Ws[2][BK][BN];
    __shared__ int toks[BM];

    const int tid = threadIdx.x;
    if (tid < BM) {
        int r = mt * BM + tid;
        toks[tid] = (r < cnt) ? g_list[p][r] : -1;
    }
    __syncthreads();

    const int w    = tid >> 5;
    const int wm   = w & 3;
    const int wn   = w >> 2;
    const int lr   = (tid >> 3) & 3;
    const int lc   = tid & 7;
    const int row0 = wm * 16 + lr * 4;
    const int col0 = wn * 32 + lc * 4;

    const int am  = tid >> 2;
    const int akq = tid & 3;
    const int bkk = tid >> 4;
    const int bc4 = tid & 15;

    const int atok = toks[am];
    const float* Wp = dec_W + (size_t)p * HS * M_SUB + nt * BN;

    float4 ra, rb;
    ra = (atok >= 0)
       ? *reinterpret_cast<const float4*>(&ctx[(size_t)atok * HS + akq * 4])
       : make_float4(0.f, 0.f, 0.f, 0.f);
    rb = *reinterpret_cast<const float4*>(&Wp[(size_t)bkk * M_SUB + bc4 * 4]);
    Xs[0][akq * 4 + 0][am] = ra.x;
    Xs[0][akq * 4 + 1][am] = ra.y;
    Xs[0][akq * 4 + 2][am] = ra.z;
    Xs[0][akq * 4 + 3][am] = ra.w;
    *reinterpret_cast<float4*>(&Ws[0][bkk][bc4 * 4]) = rb;
    __syncthreads();

    unsigned long long acc[4][2];
    #pragma unroll
    for (int i = 0; i < 4; i++) { acc[i][0] = 0ull; acc[i][1] = 0ull; }

    const int NIT = HS / BK;  // 48

    for (int it = 0; it < NIT; it++) {
        const int cur = it & 1, nxt = cur ^ 1;
        const int k0n = (it + 1) * BK;
        if (it + 1 < NIT) {
            ra = (atok >= 0)
               ? *reinterpret_cast<const float4*>(&ctx[(size_t)atok * HS + k0n + akq * 4])
               : make_float4(0.f, 0.f, 0.f, 0.f);
            rb = *reinterpret_cast<const float4*>(&Wp[(size_t)(k0n + bkk) * M_SUB + bc4 * 4]);
        }
        MICRO_FMA2(Xs[cur], Ws[cur]);
        if (it + 1 < NIT) {
            Xs[nxt][akq * 4 + 0][am] = ra.x;
            Xs[nxt][akq * 4 + 1][am] = ra.y;
            Xs[nxt][akq * 4 + 2][am] = ra.z;
            Xs[nxt][akq * 4 + 3][am] = ra.w;
            *reinterpret_cast<float4*>(&Ws[nxt][bkk][bc4 * 4]) = rb;
        }
        __syncthreads();
    }

    const int cbase = nt * BN + col0;
    const float* bp = dec_b + p * M_SUB + cbase;
    #pragma unroll
    for (int i = 0; i < 4; i++) {
        int tok = toks[row0 + i];
        if (tok < 0) continue;
        float a0, a1, a2, a3;
        unpack2(acc[i][0], a0, a1);
        unpack2(acc[i][1], a2, a3);
        float* o = g_spt + (size_t)tok * M_SUB + cbase;
        o[0] = a0 + bp[0];
        o[1] = a1 + bp[1];
        o[2] = a2 + bp[2];
        o[3] = a3 + bp[3];
    }
}

// ---------------------------------------------------------------------------
// Block reductions (256 threads)
// ---------------------------------------------------------------------------
__device__ __forceinline__ float blockMax256(float v, volatile float* red, int tid) {
    int lane = tid & 31;
    #pragma unroll
    for (int o = 16; o > 0; o >>= 1)
        v = fmaxf(v, __shfl_xor_sync(0xffffffffu, v, o));
    __syncthreads();
    if (lane == 0) red[tid >> 5] = v;
    __syncthreads();
    float r = red[0];
    #pragma unroll
    for (int i = 1; i < 8; i++) r = fmaxf(r, red[i]);
    return r;
}

__device__ __forceinline__ float blockSum256(float v, volatile float* red, int tid) {
    int lane = tid & 31;
    #pragma unroll
    for (int o = 16; o > 0; o >>= 1)
        v += __shfl_xor_sync(0xffffffffu, v, o);
    __syncthreads();
    if (lane == 0) red[tid >> 5] = v;
    __syncthreads();
    float r = red[0];
    #pragma unroll
    for (int i = 1; i < 8; i++) r += red[i];
    return r;
}

__device__ __forceinline__ void blockArgMax256(float& v, int& idx,
                                               volatile float* red, volatile int* redi,
                                               int tid) {
    int lane = tid & 31;
    #pragma unroll
    for (int o = 16; o > 0; o >>= 1) {
        float ov = __shfl_xor_sync(0xffffffffu, v, o);
        int   oi = __shfl_xor_sync(0xffffffffu, idx, o);
        if (ov > v || (ov == v && oi < idx)) { v = ov; idx = oi; }
    }
    __syncthreads();
    if (lane == 0) { red[tid >> 5] = v; redi[tid >> 5] = idx; }
    __syncthreads();
    float bv = red[0]; int bi = redi[0];
    #pragma unroll
    for (int i = 1; i < 8; i++) {
        float ov = red[i]; int oi = redi[i];
        if (ov > bv || (ov == bv && oi < bi)) { bv = ov; bi = oi; }
    }
    v = bv; idx = bi;
}

// ---------------------------------------------------------------------------
// K2: per-token row ops (float4-vectorized)
// ---------------------------------------------------------------------------
__global__ __launch_bounds__(256) void k2_row(const int* __restrict__ inp_word,
                                              const int* __restrict__ inp_pos,
                                              const int* __restrict__ inp_mask,
                                              const float* __restrict__ u_gum,
                                              const int* __restrict__ words,
                                              const float* __restrict__ psr_w,
                                              const float* __restrict__ atk_w,
                                              float* __restrict__ out) {
    const int t   = blockIdx.x;
    const int tid = threadIdx.x;
    const int w0  = inp_word[t];
    const int p   = inp_pos[t];
    const bool mk = inp_mask[t] != 0;

    if (p >= P_EXP) {
        if (tid == 0) {
            out[OFF_WORD + t] = (float)w0;
            out[OFF_CPY + t]  = mk ? 1.0f : 0.0f;
            out[OFF_OBF + t]  = 0.0f;
            out[OFF_PRI + t]  = 0.0f;
        }
        const float4* ps = (const float4*)(psr_w + (size_t)w0 * D_EMB);
        const float4* as = (const float4*)(atk_w + (size_t)w0 * D_EMB);
        float4* po = (float4*)(out + OFF_PSR + (size_t)t * D_EMB);
        float4* ao = (float4*)(out + OFF_ATK + (size_t)t * D_EMB);
        for (int d = tid; d < D_EMB / 4; d += 256) { po[d] = ps[d]; ao[d] = as[d]; }
        return;
    }

    __shared__ float red[8];
    __shared__ int   redi[8];

    float4* rowv = (float4*)(g_spt + (size_t)t * M_SUB);
    const float4* uv = (const float4*)(u_gum + (size_t)t * M_SUB);

    float4 lv = rowv[tid];
    float4 uu4 = uv[tid];
    float l[4] = {lv.x, lv.y, lv.z, lv.w};
    float u4[4] = {uu4.x, uu4.y, uu4.z, uu4.w};
    float z[4];
    #pragma unroll
    for (int k = 0; k < 4; k++) {
        float uu = fminf(fmaxf(u4[k], 1e-6f), 1.0f - 1e-6f);
        z[k] = l[k] - logf(-logf(uu));
    }

    // log-softmax over logits
    float m1 = fmaxf(fmaxf(l[0], l[1]), fmaxf(l[2], l[3]));
    m1 = blockMax256(m1, red, tid);
    float s1 = 0.0f;
    #pragma unroll
    for (int k = 0; k < 4; k++) s1 += expf(l[k] - m1);
    s1 = blockSum256(s1, red, tid);
    const float lse = m1 + logf(s1);

    // entropy term
    float se = 0.0f;
    #pragma unroll
    for (int k = 0; k < 4; k++) {
        float ps = l[k] - lse;
        se += ps * expf(ps);
    }
    se = blockSum256(se, red, tid);
    if (tid == 0) g_negent[t] = -se;

    // gumbel softmax: argmax + normalize
    float mv = z[0]; int midx = tid * 4;
    #pragma unroll
    for (int k = 1; k < 4; k++) {
        if (z[k] > mv) { mv = z[k]; midx = tid * 4 + k; }
    }
    blockArgMax256(mv, midx, red, redi, tid);

    float s2 = 0.0f;
    #pragma unroll
    for (int k = 0; k < 4; k++) s2 += expf(z[k] - mv);
    s2 = blockSum256(s2, red, tid);
    const float inv = 1.0f / s2;
    float4 sv;
    sv.x = expf(z[0] - mv) * inv;
    sv.y = expf(z[1] - mv) * inv;
    sv.z = expf(z[2] - mv) * inv;
    sv.w = expf(z[3] - mv) * inv;
    rowv[tid] = sv;

    if (tid == 0) {
        int aw = words[p * M_SUB + midx];
        out[OFF_WORD + t] = (float)aw;
        out[OFF_CPY + t]  = (aw == w0 && mk) ? 1.0f : 0.0f;
        out[OFF_OBF + t]  = 1.0f;
        out[OFF_PRI + t]  = (p < 4) ? 1.0f : 0.0f;
    }
}

// ---------------------------------------------------------------------------
// K3: out[t, :] = spt[t] @ gather(table, words[p])  (combined psr|atk columns)
// ---------------------------------------------------------------------------
__global__ __launch_bounds__(256) void k3_gemm(const float* __restrict__ psr_w,
                                               const float* __restrict__ atk_w,
                                               const int* __restrict__ words,
                                               float* __restrict__ out) {
    const int p  = blockIdx.z;
    const int mt = blockIdx.y;
    const int nt = blockIdx.x;
    const int cnt = g_cnt[p];
    if (mt * BM >= cnt) return;

    __shared__ __align__(16) float As[2][BK][BM];
    __shared__ __align__(16) float Bs[2][BK][BN];
    __shared__ int toks[BM];

    const int tid = threadIdx.x;
    if (tid < BM) {
        int r = mt * BM + tid;
        toks[tid] = (r < cnt) ? g_list[p][r] : -1;
    }
    __syncthreads();

    const int w    = tid >> 5;
    const int wm   = w & 3;
    const int wn   = w >> 2;
    const int lr   = (tid >> 3) & 3;
    const int lc   = tid & 7;
    const int row0 = wm * 16 + lr * 4;
    const int col0 = wn * 32 + lc * 4;

    const int am  = tid >> 2;
    const int akq = tid & 3;
    const int bkk = tid >> 4;
    const int bc4 = tid & 15;

    const int atok = toks[am];

    const int cbase0  = nt * BN;
    const bool is_psr = (cbase0 < D_EMB);
    const float* tab  = is_psr ? psr_w : atk_w;
    const int dbase   = is_psr ? cbase0 : (cbase0 - D_EMB);
    const int* wp     = words + p * M_SUB;

    float4 ra, rb;
    ra = (atok >= 0)
       ? *reinterpret_cast<const float4*>(&g_spt[(size_t)atok * M_SUB + akq * 4])
       : make_float4(0.f, 0.f, 0.f, 0.f);
    {
        int wr = __ldg(&wp[bkk]);
        rb = *reinterpret_cast<const float4*>(&tab[(size_t)wr * D_EMB + dbase + bc4 * 4]);
    }
    As[0][akq * 4 + 0][am] = ra.x;
    As[0][akq * 4 + 1][am] = ra.y;
    As[0][akq * 4 + 2][am] = ra.z;
    As[0][akq * 4 + 3][am] = ra.w;
    *reinterpret_cast<float4*>(&Bs[0][bkk][bc4 * 4]) = rb;
    __syncthreads();

    unsigned long long acc[4][2];
    #pragma unroll
    for (int i = 0; i < 4; i++) { acc[i][0] = 0ull; acc[i][1] = 0ull; }

    const int NIT = M_SUB / BK;  // 64

    for (int it = 0; it < NIT; it++) {
        const int cur = it & 1, nxt = cur ^ 1;
        const int k0n = (it + 1) * BK;
        if (it + 1 < NIT) {
            ra = (atok >= 0)
               ? *reinterpret_cast<const float4*>(&g_spt[(size_t)atok * M_SUB + k0n + akq * 4])
               : make_float4(0.f, 0.f, 0.f, 0.f);
            int wr = __ldg(&wp[k0n + bkk]);
            rb = *reinterpret_cast<const float4*>(&tab[(size_t)wr * D_EMB + dbase + bc4 * 4]);
        }
        MICRO_FMA2(As[cur], Bs[cur]);
        if (it + 1 < NIT) {
            As[nxt][akq * 4 + 0][am] = ra.x;
            As[nxt][akq * 4 + 1][am] = ra.y;
            As[nxt][akq * 4 + 2][am] = ra.z;
            As[nxt][akq * 4 + 3][am] = ra.w;
            *reinterpret_cast<float4*>(&Bs[nxt][bkk][bc4 * 4]) = rb;
        }
        __syncthreads();
    }

    const size_t obase = (is_psr ? (size_t)OFF_PSR : (size_t)OFF_ATK);
    const int dcol = dbase + col0;
    #pragma unroll
    for (int i = 0; i < 4; i++) {
        int tok = toks[row0 + i];
        if (tok < 0) continue;
        float a0, a1, a2, a3;
        unpack2(acc[i][0], a0, a1);
        unpack2(acc[i][1], a2, a3);
        float* o = out + obase + (size_t)tok * D_EMB + dcol;
        o[0] = a0; o[1] = a1; o[2] = a2; o[3] = a3;
    }
}

// ---------------------------------------------------------------------------
// K4: deterministic entropy finalize
// ---------------------------------------------------------------------------
__global__ void k4_ent(const int* __restrict__ inp_pos, float* __restrict__ out) {
    __shared__ float sh[256];
    __shared__ int   shc[256];
    __shared__ float ent_s;
    const int tid = threadIdx.x;
    if (tid == 0) ent_s = 0.0f;

    for (int p = 0; p < P_EXP; p++) {
        float s = 0.0f; int c = 0;
        for (int t = tid; t < T_TOK; t += 256) {
            if (inp_pos[t] == p) { s += g_negent[t]; c++; }
        }
        sh[tid] = s; shc[tid] = c;
        __syncthreads();
        for (int o = 128; o > 0; o >>= 1) {
            if (tid < o) { sh[tid] += sh[tid + o]; shc[tid] += shc[tid + o]; }
            __syncthreads();
        }
        if (tid == 0 && shc[0] > 0)
            ent_s += sh[0] / ((float)shc[0] * (float)M_SUB);
        __syncthreads();
    }
    if (tid == 0) out[OFF_ENT] = -ent_s;
}

// ---------------------------------------------------------------------------
// Entry point
// ---------------------------------------------------------------------------
extern "C" void kernel_launch(void* const* d_in, const int* in_sizes, int n_in,
                              void* d_out, int out_size) {
    const int*      inp_word = (const int*)d_in[0];
    const int*      inp_pos  = (const int*)d_in[1];
    const int*      inp_mask = (const int*)d_in[2];   // JAX bool -> int32
    const float*    ctx      = (const float*)d_in[3];
    const float*    dec_W    = (const float*)d_in[4];
    const float*    dec_b    = (const float*)d_in[5];
    const float*    psr_w    = (const float*)d_in[6];
    const float*    atk_w    = (const float*)d_in[7];
    const int*      words    = (const int*)d_in[8];
    const float*    u_gum    = (const float*)d_in[9];
    float*          out      = (float*)d_out;

    (void)in_sizes; (void)n_in; (void)out_size;

    k0_compact<<<1, 256>>>(inp_pos);
    k1_gemm<<<dim3(M_SUB / BN, T_TOK / BM, P_EXP), 256>>>(ctx, dec_W, dec_b);
    k2_row<<<T_TOK, 256>>>(inp_word, inp_pos, inp_mask, u_gum, words,
                           psr_w, atk_w, out);
    k3_gemm<<<dim3((2 * D_EMB) / BN, T_TOK / BM, P_EXP), 256>>>(psr_w, atk_w,
                                                                words, out);
    k4_ent<<<1, 256>>>(inp_pos, out);
}